// round 15
// baseline (speedup 1.0000x reference)
#include <cuda_runtime.h>
#include <math.h>

#define HW   16384
#define B_   4
#define NCH  67

// ---------------- scratch ------------------------------------------------------
__device__ float g_xcat0[B_*NCH*HW];
__device__ float g_xcat1[B_*NCH*HW];
__device__ float g_off  [B_*18*HW];
__device__ float g_mask [B_*9*HW];
__device__ float g_xfin [B_*3*HW];
__device__ float g_ch   [B_*16*27];
__device__ float g_pool [B_*3];

__device__ __forceinline__ float sigm(float v){ return 1.f/(1.f+__expf(-v)); }

// ---- packed fp32x2 helpers ----------------------------------------------------
typedef unsigned long long ull;
__device__ __forceinline__ ull dup2(float v){
    ull r; asm("mov.b64 %0, {%1, %1};" : "=l"(r) : "f"(v)); return r;
}
__device__ __forceinline__ void ffma2(ull &d, ull a, ull b){
    asm("fma.rn.f32x2 %0, %1, %2, %0;" : "+l"(d) : "l"(a), "l"(b));
}
__device__ __forceinline__ ull add2(ull a, ull b){
    ull r; asm("add.rn.f32x2 %0, %1, %2;" : "=l"(r) : "l"(a), "l"(b)); return r;
}
__device__ __forceinline__ float2 unpk(ull v){
    float2 f; asm("mov.b64 {%0, %1}, %2;" : "=f"(f.x), "=f"(f.y) : "l"(v)); return f;
}

// ---------------- 0) copy LR into both xcat buffers (also shifts ncu index) ---
__global__ void copy_lr_kernel(const float* __restrict__ X)
{
    int i = blockIdx.x*256 + threadIdx.x;
    if (i >= B_*3*HW/4) return;
    int b = i / (3*HW/4), rem = i - b*(3*HW/4);
    float4 v = ((const float4*)X)[i];
    ((float4*)(g_xcat0 + (b*NCH + 64)*HW))[rem] = v;
    ((float4*)(g_xcat1 + (b*NCH + 64)*HW))[rem] = v;
}

// ---------------- 1) ConvLSTM: row-CTA, smem-staged, f32x2 k-pairs ------------
__global__ __launch_bounds__(256) void lstm_kernel(
    const float* __restrict__ X, const float* __restrict__ w,
    const float* __restrict__ bias,
    float* __restrict__ hid, float* __restrict__ cell, float* __restrict__ xcat)
{
    __shared__ float sX[9*132];
    __shared__ float2 sW2[32*3*28];
    __shared__ float2 sB2[32*3];

    int tid = threadIdx.x;
    int b = blockIdx.y, y = blockIdx.x;

    for (int i = tid; i < 2688; i += 256) {
        int kp = i / 84, rem = i - kp*84;
        int g = rem / 28, t = rem - g*28;
        int gbase = (g == 0) ? 0 : (g == 1) ? 128 : 192;
        float v0 = 0.f, v1 = 0.f;
        if (t < 27) {
            v0 = w[(gbase + 2*kp    )*603 + t];
            v1 = w[(gbase + 2*kp + 1)*603 + t];
        }
        sW2[i] = make_float2(v0, v1);
    }
    if (tid < 96) {
        int kp = tid / 3, g = tid - kp*3;
        int gbase = (g == 0) ? 0 : (g == 1) ? 128 : 192;
        sB2[tid] = make_float2(bias[gbase + 2*kp], bias[gbase + 2*kp + 1]);
    }
    if (tid < 9) {
        float* row = sX + tid*132;
        row[0] = 0.f; row[129] = 0.f; row[130] = 0.f; row[131] = 0.f;
    }
    for (int idx = tid; idx < 288; idx += 256) {
        int row9 = idx >> 5, q = idx & 31;
        int c = row9 / 3, r = row9 - c*3;
        int gy = y - 1 + r;
        float4 v = make_float4(0.f, 0.f, 0.f, 0.f);
        if (gy >= 0 && gy < 128)
            v = *(const float4*)(X + (b*3 + c)*HW + gy*128 + q*4);
        float* dst = sX + row9*132 + 1 + q*4;
        dst[0] = v.x; dst[1] = v.y; dst[2] = v.z; dst[3] = v.w;
    }
    __syncthreads();

    int px = tid & 127, kh = tid >> 7;

    ull win[28];
    #pragma unroll
    for (int c = 0; c < 3; c++)
        #pragma unroll
        for (int r = 0; r < 3; r++)
            #pragma unroll
            for (int q = 0; q < 3; q++)
                win[c*9 + r*3 + q] = dup2(sX[(c*3 + r)*132 + px + q]);
    win[27] = 0ull;

    int pix = y*128 + px;
    int kp0 = kh*16;
    #pragma unroll 1
    for (int kp = kp0; kp < kp0 + 16; kp++) {
        ull aI = *(const ull*)&sB2[kp*3 + 0];
        ull aO = *(const ull*)&sB2[kp*3 + 1];
        ull aG = *(const ull*)&sB2[kp*3 + 2];
        const ulonglong2* wI = (const ulonglong2*)(sW2 + (kp*3 + 0)*28);
        const ulonglong2* wO = (const ulonglong2*)(sW2 + (kp*3 + 1)*28);
        const ulonglong2* wG = (const ulonglong2*)(sW2 + (kp*3 + 2)*28);
        #pragma unroll
        for (int t2 = 0; t2 < 14; t2++) {
            ulonglong2 wi = wI[t2];
            ffma2(aI, wi.x, win[2*t2]); ffma2(aI, wi.y, win[2*t2 + 1]);
            ulonglong2 wo = wO[t2];
            ffma2(aO, wo.x, win[2*t2]); ffma2(aO, wo.y, win[2*t2 + 1]);
            ulonglong2 wg = wG[t2];
            ffma2(aG, wg.x, win[2*t2]); ffma2(aG, wg.y, win[2*t2 + 1]);
        }
        float2 ai = unpk(aI), ao = unpk(aO), ag = unpk(aG);
        float c0 = sigm(ai.x)*tanhf(ag.x);
        float c1 = sigm(ai.y)*tanhf(ag.y);
        float h0 = sigm(ao.x)*tanhf(c0);
        float h1 = sigm(ao.y)*tanhf(c1);
        int k0 = 2*kp;
        hid [(b*64 + k0    )*HW + pix] = h0;
        hid [(b*64 + k0 + 1)*HW + pix] = h1;
        cell[(b*64 + k0    )*HW + pix] = c0;
        cell[(b*64 + k0 + 1)*HW + pix] = c1;
        xcat[(b*NCH + k0    )*HW + pix] = h0;
        xcat[(b*NCH + k0 + 1)*HW + pix] = h1;
    }
}

// ---------------- 2) offset/mask conv, f32x2 packed GEMM ----------------------
__global__ __launch_bounds__(256) void conv_off_kernel(
    const float* __restrict__ xcat,
    const float* __restrict__ w0, const float* __restrict__ b0,
    const float* __restrict__ w1, const float* __restrict__ b1,
    float* __restrict__ out0, float* __restrict__ out1)
{
    __shared__ float sTile[16*3*132];
    __shared__ float sW[144*32];

    int tid = threadIdx.x;
    int pg = tid & 31;
    int og = tid >> 5;
    int b = blockIdx.y, y = blockIdx.x;
    int y0 = y - 1;

    ull acc[2][4];
    #pragma unroll
    for (int q = 0; q < 2; q++)
        #pragma unroll
        for (int p = 0; p < 4; p++) acc[q][p] = 0ull;

    for (int c0 = 0; c0 < 67; c0 += 16) {
        int cnt = (67 - c0) < 16 ? (67 - c0) : 16;
        for (int i = tid; i < cnt*3; i += 256) {
            int c = i / 3, r = i - c*3;
            float* row = sTile + c*396 + r*132;
            row[0] = 0.f; row[129] = 0.f; row[130] = 0.f; row[131] = 0.f;
        }
        for (int i = tid; i < cnt*96; i += 256) {
            int c = i / 96, rem = i - c*96;
            int r = rem >> 5, q = rem & 31;
            int gy = y0 + r;
            const float* src = xcat + (b*NCH + c0 + c)*HW;
            float4 v = make_float4(0.f, 0.f, 0.f, 0.f);
            if (gy >= 0 && gy < 128) v = *(const float4*)(src + gy*128 + q*4);
            float* dst = sTile + c*396 + r*132 + 1 + q*4;
            dst[0] = v.x; dst[1] = v.y; dst[2] = v.z; dst[3] = v.w;
        }
        int c09 = c0*9;
        for (int i = tid; i < cnt*288; i += 256) {
            int o = i & 31, tdx = i >> 5;
            float wv = 0.f;
            if (o < 18)      wv = w0[o*603 + c09 + tdx];
            else if (o < 27) wv = w1[(o-18)*603 + c09 + tdx];
            sW[tdx*32 + o] = wv;
        }
        __syncthreads();

        for (int c = 0; c < cnt; c++) {
            #pragma unroll
            for (int ky = 0; ky < 3; ky++) {
                const float* rb = sTile + c*396 + ky*132 + pg*4;
                float4 a4 = *(const float4*)rb;
                float2 a2 = *(const float2*)(rb + 4);
                ull vv[6];
                vv[0] = dup2(a4.x); vv[1] = dup2(a4.y); vv[2] = dup2(a4.z);
                vv[3] = dup2(a4.w); vv[4] = dup2(a2.x); vv[5] = dup2(a2.y);
                #pragma unroll
                for (int kx = 0; kx < 3; kx++) {
                    ulonglong2 w = *(const ulonglong2*)(sW + (c*9 + ky*3 + kx)*32 + og*4);
                    #pragma unroll
                    for (int p = 0; p < 4; p++) {
                        ffma2(acc[0][p], w.x, vv[kx + p]);
                        ffma2(acc[1][p], w.y, vv[kx + p]);
                    }
                }
            }
        }
        __syncthreads();
    }

    int pixb = y*128 + pg*4;
    #pragma unroll
    for (int wp = 0; wp < 2; wp++) {
        int o0 = og*4 + 2*wp;
        float2 a0 = unpk(acc[wp][0]), a1 = unpk(acc[wp][1]);
        float2 a2 = unpk(acc[wp][2]), a3 = unpk(acc[wp][3]);
        if (o0 < 18) {
            float bb = b0[o0];
            *(float4*)(out0 + (b*18 + o0)*HW + pixb) =
                make_float4(a0.x+bb, a1.x+bb, a2.x+bb, a3.x+bb);
        } else if (o0 < 27) {
            float bb = b1[o0-18];
            *(float4*)(out1 + (b*9 + (o0-18))*HW + pixb) =
                make_float4(2.f*sigm(a0.x+bb), 2.f*sigm(a1.x+bb),
                            2.f*sigm(a2.x+bb), 2.f*sigm(a3.x+bb));
        }
        int o1 = o0 + 1;
        if (o1 < 18) {
            float bb = b0[o1];
            *(float4*)(out0 + (b*18 + o1)*HW + pixb) =
                make_float4(a0.y+bb, a1.y+bb, a2.y+bb, a3.y+bb);
        } else if (o1 < 27) {
            float bb = b1[o1-18];
            *(float4*)(out1 + (b*9 + (o1-18))*HW + pixb) =
                make_float4(2.f*sigm(a0.y+bb), 2.f*sigm(a1.y+bb),
                            2.f*sigm(a2.y+bb), 2.f*sigm(a3.y+bb));
        }
    }
}

// ---------------- 2b) small direct conv (final 3-out fuse conv) ---------------
template<int COUT>
__global__ __launch_bounds__(256) void conv_small_kernel(
    const float* __restrict__ xcat,
    const float* __restrict__ w0, const float* __restrict__ b0,
    float* __restrict__ out0)
{
    __shared__ float sT[16*10*34];
    __shared__ float sW[COUT*16*9];
    int tid = threadIdx.x;
    int tx = tid & 31, ty = tid >> 5;
    int b = blockIdx.z;
    int x = blockIdx.x*32 + tx, y = blockIdx.y*8 + ty;
    int gx0 = blockIdx.x*32 - 1, gy0 = blockIdx.y*8 - 1;

    float acc[COUT];
    #pragma unroll
    for (int o = 0; o < COUT; o++) acc[o] = 0.f;

    for (int c0 = 0; c0 < 67; c0 += 16) {
        int cnt = (67 - c0) < 16 ? (67 - c0) : 16;
        for (int i = tid; i < cnt*340; i += 256) {
            int c = i / 340, rem = i - c*340;
            int r = rem / 34, col = rem - r*34;
            int gy = gy0 + r, gx = gx0 + col;
            const float* src = xcat + (b*NCH + c0 + c)*HW;
            sT[i] = (gy >= 0 && gy < 128 && gx >= 0 && gx < 128)
                  ? src[gy*128 + gx] : 0.f;
        }
        int wtot = COUT*cnt*9;
        for (int i = tid; i < wtot; i += 256) {
            int o = i / (cnt*9), rem = i - o*(cnt*9);
            sW[o*144 + rem] = w0[o*603 + c0*9 + rem];
        }
        __syncthreads();
        for (int c = 0; c < cnt; c++) {
            float win[9];
            #pragma unroll
            for (int r = 0; r < 3; r++)
                #pragma unroll
                for (int q = 0; q < 3; q++)
                    win[r*3+q] = sT[c*340 + (ty+r)*34 + (tx+q)];
            #pragma unroll
            for (int o = 0; o < COUT; o++) {
                #pragma unroll
                for (int t = 0; t < 9; t++)
                    acc[o] = fmaf(sW[o*144 + c*9 + t], win[t], acc[o]);
            }
        }
        __syncthreads();
    }
    int pix = y*128 + x;
    #pragma unroll
    for (int o = 0; o < COUT; o++)
        out0[(b*COUT + o)*HW + pix] = acc[o] + b0[o];
}

// ---------------- 3) deform: double-buffered chunk-18 pipeline, 4 CTA/SM ------
#define DF_SIDX   4608
#define DF_SV     (4608 + 1152)
#define SV_STRIDE (18*132)
#define DF_SWC    (DF_SV + 2*SV_STRIDE)
#define SWC_STRIDE (18*64)
#define DF_SMEM_BYTES ((DF_SWC + 2*SWC_STRIDE) * 4)
#define NCHUNK 34

__global__ __launch_bounds__(256, 4) void deform_kernel(
    const float* __restrict__ xcat,
    const float* __restrict__ wmain, const float* __restrict__ bias,
    float* __restrict__ out)
{
    extern __shared__ float smem[];
    float4* sWt = (float4*)smem;
    int*    sIdx= (int*)(smem + DF_SIDX);
    float*  sV  = smem + DF_SV;
    float*  sWc = smem + DF_SWC;

    int tid = threadIdx.x;
    int b = blockIdx.y, y = blockIdx.x;

    // ---- Phase A: bilinear meta (9 taps x 128 px) ----
    for (int e = tid; e < 1152; e += 256) {
        int p = e & 127, k = e >> 7;
        int pix = y*128 + p;
        float offy = g_off [(b*18 + 2*k    )*HW + pix];
        float offx = g_off [(b*18 + 2*k + 1)*HW + pix];
        float m    = g_mask[(b*9  + k      )*HW + pix];
        int ky = k / 3, kx = k - ky*3;
        float py = (float)(y + ky - 1) + offy;
        float px = (float)(p + kx - 1) + offx;
        float fy = floorf(py), fx = floorf(px);
        float wy = py - fy,    wx = px - fx;
        int iy = (int)fy, ix = (int)fx;
        bool vy0 = (iy   >= 0 && iy   <= 127);
        bool vy1 = (iy+1 >= 0 && iy+1 <= 127);
        bool vx0 = (ix   >= 0 && ix   <= 127);
        bool vx1 = (ix+1 >= 0 && ix+1 <= 127);
        float4 wv;
        wv.x = (1.f-wy)*(1.f-wx)*m * ((vy0 && vx0) ? 1.f : 0.f);
        wv.y = (1.f-wy)*wx      *m * ((vy0 && vx1) ? 1.f : 0.f);
        wv.z = wy*(1.f-wx)      *m * ((vy1 && vx0) ? 1.f : 0.f);
        wv.w = wy*wx            *m * ((vy1 && vx1) ? 1.f : 0.f);
        sWt[e] = wv;
        int iy0 = min(max(iy,   0), 127), iy1 = min(max(iy+1, 0), 127);
        int ix0 = min(max(ix,   0), 127), ix1 = min(max(ix+1, 0), 127);
        sIdx[e] = iy0 | (iy1 << 8) | (ix0 << 16) | (ix1 << 24);
    }

    const float* xb = xcat + b*NCH*HW;
    int pg = tid & 31, og = tid >> 5;

    ull acc[4][4];
    #pragma unroll
    for (int q = 0; q < 4; q++)
        #pragma unroll
        for (int p = 0; p < 4; p++) acc[q][p] = 0ull;

    auto stage = [&](int c, int buf) {
        int c0 = c*18;
        int cnt = (603 - c0) < 18 ? (603 - c0) : 18;
        int nch = cnt / 9;
        float* sVb = sV + buf*SV_STRIDE;
        float* sWb = sWc + buf*SWC_STRIDE;
        for (int i = tid; i < 18*64; i += 256) {
            int o = i & 63, j = i >> 6;
            sWb[j*64 + o] = (j < cnt) ? wmain[o*603 + c0 + j] : 0.f;
        }
        if (cnt < 18)
            for (int i = tid; i < (18 - cnt)*132; i += 256)
                sVb[cnt*132 + i] = 0.f;
        int cbase = (c0/9) * HW;
        #pragma unroll 2
        for (int g = tid; g < 1152; g += 256) {
            int p = g & 127, k = g >> 7;
            float4 wt = sWt[g];
            int pk = sIdx[g];
            int iy0 =  pk        & 255, iy1 = (pk >> 8)  & 255;
            int ix0 = (pk >> 16) & 255, ix1 = (pk >> 24) & 255;
            int i0 = cbase + iy0*128 + ix0;
            int i1 = cbase + iy0*128 + ix1;
            int i2 = cbase + iy1*128 + ix0;
            int i3 = cbase + iy1*128 + ix1;
            float* sv = sVb + k*132 + p;
            if (nch == 2) {
                float a0 = __ldg(xb + i0),      a1 = __ldg(xb + i1);
                float a2 = __ldg(xb + i2),      a3 = __ldg(xb + i3);
                float b0 = __ldg(xb + i0 + HW), b1 = __ldg(xb + i1 + HW);
                float b2 = __ldg(xb + i2 + HW), b3 = __ldg(xb + i3 + HW);
                sv[0]     = wt.x*a0 + wt.y*a1 + wt.z*a2 + wt.w*a3;
                sv[9*132] = wt.x*b0 + wt.y*b1 + wt.z*b2 + wt.w*b3;
            } else {
                float a0 = __ldg(xb + i0), a1 = __ldg(xb + i1);
                float a2 = __ldg(xb + i2), a3 = __ldg(xb + i3);
                sv[0] = wt.x*a0 + wt.y*a1 + wt.z*a2 + wt.w*a3;
            }
        }
    };

    __syncthreads();
    stage(0, 0);
    __syncthreads();

    for (int c = 0; c < NCHUNK; c++) {
        int buf = c & 1;
        if (c + 1 < NCHUNK) stage(c + 1, buf ^ 1);

        const float* vp = sV + buf*SV_STRIDE + pg*4;
        const float* wp_ = sWc + buf*SWC_STRIDE + og*8;
        #pragma unroll 6
        for (int j = 0; j < 18; j++) {
            ulonglong2 wA = *(const ulonglong2*)(wp_ + j*64);
            ulonglong2 wB = *(const ulonglong2*)(wp_ + j*64 + 4);
            float4 v = *(const float4*)(vp + j*132);
            ull v0 = dup2(v.x), v1 = dup2(v.y), v2 = dup2(v.z), v3 = dup2(v.w);
            ffma2(acc[0][0], wA.x, v0); ffma2(acc[0][1], wA.x, v1);
            ffma2(acc[0][2], wA.x, v2); ffma2(acc[0][3], wA.x, v3);
            ffma2(acc[1][0], wA.y, v0); ffma2(acc[1][1], wA.y, v1);
            ffma2(acc[1][2], wA.y, v2); ffma2(acc[1][3], wA.y, v3);
            ffma2(acc[2][0], wB.x, v0); ffma2(acc[2][1], wB.x, v1);
            ffma2(acc[2][2], wB.x, v2); ffma2(acc[2][3], wB.x, v3);
            ffma2(acc[3][0], wB.y, v0); ffma2(acc[3][1], wB.y, v1);
            ffma2(acc[3][2], wB.y, v2); ffma2(acc[3][3], wB.y, v3);
        }
        __syncthreads();
    }

    int pixb = y*128 + pg*4;
    #pragma unroll
    for (int wp = 0; wp < 4; wp++) {
        int o0 = og*8 + 2*wp;
        float2 a0 = unpk(acc[wp][0]), a1 = unpk(acc[wp][1]);
        float2 a2 = unpk(acc[wp][2]), a3 = unpk(acc[wp][3]);
        float bb0 = bias[o0], bb1 = bias[o0+1];
        *(float4*)(out + (b*NCH + o0)*HW + pixb) =
            make_float4(a0.x+bb0, a1.x+bb0, a2.x+bb0, a3.x+bb0);
        *(float4*)(out + (b*NCH + o0+1)*HW + pixb) =
            make_float4(a0.y+bb1, a1.y+bb1, a2.y+bb1, a3.y+bb1);
    }
}

// ---------------- 4) global average pool --------------------------------------
__global__ void pool_kernel(const float* __restrict__ xf)
{
    __shared__ float red[256];
    int bc = blockIdx.x, tid = threadIdx.x;
    float s = 0.f;
    const float* p = xf + bc*HW;
    for (int i = tid; i < HW; i += 256) s += p[i];
    red[tid] = s; __syncthreads();
    for (int st = 128; st > 0; st >>= 1) {
        if (tid < st) red[tid] += red[tid + st];
        __syncthreads();
    }
    if (tid == 0) g_pool[bc] = red[0] * (1.f/HW);
}

// ---------------- 5) channel-filter MLP ---------------------------------------
__global__ void ch_kernel(const float* __restrict__ ch_w1, const float* __restrict__ ch_b1,
                          const float* __restrict__ ch_w2, const float* __restrict__ ch_b2)
{
    int t = threadIdx.x;
    if (t >= 64) return;
    int b = t >> 4, s = t & 15;
    float h1[4];
    #pragma unroll
    for (int m = 0; m < 4; m++) {
        float a = ch_b1[s*4 + m];
        #pragma unroll
        for (int c = 0; c < 3; c++) a = fmaf(g_pool[b*3 + c], ch_w1[(s*4 + m)*3 + c], a);
        h1[m] = fmaxf(a, 0.f);
    }
    for (int k = 0; k < 27; k++) {
        float a = ch_b2[s*27 + k];
        #pragma unroll
        for (int m = 0; m < 4; m++) a = fmaf(h1[m], ch_w2[(s*27 + k)*4 + m], a);
        g_ch[(b*16 + s)*27 + k] = a;
    }
}

// ---------------- 6) DDF up: f32x2 s-pair packed, 2 threads/px ----------------
__global__ __launch_bounds__(256) void ddf_kernel(
    const float* __restrict__ spw, const float* __restrict__ spb,
    float* __restrict__ out)
{
    __shared__ __align__(16) float2 sSpw2[8*9*28];
    __shared__ float2 sSpb2[72];
    __shared__ float2 sCh2[216];
    __shared__ float sX[3*3*132];

    int tid = threadIdx.x;
    int b = blockIdx.y, y = blockIdx.x;

    for (int idx = tid; idx < 2016; idx += 256) {
        int i = idx / 252, rem = idx - i*252;
        int k = rem / 28, j = rem - k*28;
        float v0 = 0.f, v1 = 0.f;
        if (j < 27) {
            v0 = spw[((2*i  )*9 + k)*27 + j];
            v1 = spw[((2*i+1)*9 + k)*27 + j];
        }
        sSpw2[idx] = make_float2(v0, v1);
    }
    if (tid < 72) {
        int i = tid / 9, k = tid - i*9;
        sSpb2[tid] = make_float2(spb[(2*i)*9 + k], spb[(2*i+1)*9 + k]);
    }
    if (tid < 216) {
        int i = tid / 27, j = tid - i*27;
        sCh2[tid] = make_float2(g_ch[b*432 + (2*i)*27 + j],
                                g_ch[b*432 + (2*i+1)*27 + j]);
    }
    if (tid < 9) {
        float* row = sX + tid*132;
        row[0] = 0.f; row[129] = 0.f; row[130] = 0.f; row[131] = 0.f;
    }
    for (int idx = tid; idx < 288; idx += 256) {
        int row9 = idx >> 5, q = idx & 31;
        int c = row9 / 3, r = row9 - c*3;
        int gy = y - 1 + r;
        float4 v = make_float4(0.f, 0.f, 0.f, 0.f);
        if (gy >= 0 && gy < 128)
            v = *(const float4*)(g_xfin + (b*3 + c)*HW + gy*128 + q*4);
        float* dst = sX + row9*132 + 1 + q*4;
        dst[0] = v.x; dst[1] = v.y; dst[2] = v.z; dst[3] = v.w;
    }
    __syncthreads();

    int px = tid & 127, half = tid >> 7;

    ull winD[28];
    #pragma unroll
    for (int c = 0; c < 3; c++)
        #pragma unroll
        for (int r = 0; r < 3; r++)
            #pragma unroll
            for (int q = 0; q < 3; q++)
                winD[c*9 + r*3 + q] = dup2(sX[(c*3 + r)*132 + px + q]);
    winD[27] = 0ull;

    float* ob = out + b*3*(512*512);
    int i0 = half*4;
    #pragma unroll 1
    for (int i = i0; i < i0 + 4; i++) {
        ull a0 = 0ull, a1 = 0ull, a2 = 0ull;
        #pragma unroll
        for (int k = 0; k < 9; k++) {
            ull spv = *(const ull*)&sSpb2[i*9 + k];
            const ulonglong2* w2 = (const ulonglong2*)(sSpw2 + (i*9 + k)*28);
            #pragma unroll
            for (int j2 = 0; j2 < 14; j2++) {
                ulonglong2 w = w2[j2];
                ffma2(spv, w.x, winD[j2*2]);
                ffma2(spv, w.y, winD[j2*2 + 1]);
            }
            ull t0 = add2(*(const ull*)&sCh2[i*27 + k],      spv);
            ull t1 = add2(*(const ull*)&sCh2[i*27 + 9 + k],  spv);
            ull t2 = add2(*(const ull*)&sCh2[i*27 + 18 + k], spv);
            ffma2(a0, winD[k],      t0);
            ffma2(a1, winD[9 + k],  t1);
            ffma2(a2, winD[18 + k], t2);
        }
        float2 r0 = unpk(a0), r1 = unpk(a1), r2 = unpk(a2);
        int s0 = 2*i, s1 = 2*i + 1;
        int oy0 = (y << 2) + (s0 >> 2), ox0 = (px << 2) + (s0 & 3);
        int oy1 = (y << 2) + (s1 >> 2), ox1 = (px << 2) + (s1 & 3);
        ob[0*262144 + oy0*512 + ox0] = fminf(fmaxf(r0.x, 0.f), 255.f);
        ob[1*262144 + oy0*512 + ox0] = fminf(fmaxf(r1.x, 0.f), 255.f);
        ob[2*262144 + oy0*512 + ox0] = fminf(fmaxf(r2.x, 0.f), 255.f);
        ob[0*262144 + oy1*512 + ox1] = fminf(fmaxf(r0.y, 0.f), 255.f);
        ob[1*262144 + oy1*512 + ox1] = fminf(fmaxf(r1.y, 0.f), 255.f);
        ob[2*262144 + oy1*512 + ox1] = fminf(fmaxf(r2.y, 0.f), 255.f);
    }
}

// ---------------- host orchestration ------------------------------------------
extern "C" void kernel_launch(void* const* d_in, const int* in_sizes, int n_in,
                              void* d_out, int out_size)
{
    const float* X      = (const float*)d_in[0];
    const float* lstm_w = (const float*)d_in[1];
    const float* lstm_b = (const float*)d_in[2];
    const float* dw[3][6];
    for (int i = 0; i < 3; i++)
        for (int j = 0; j < 6; j++)
            dw[i][j] = (const float*)d_in[3 + i*6 + j];   // ow, ob, mw, mb, w, b
    const float* conv_w = (const float*)d_in[21];
    const float* conv_b = (const float*)d_in[22];
    const float* sp_w   = (const float*)d_in[23];
    const float* sp_b   = (const float*)d_in[24];
    const float* ch_w1  = (const float*)d_in[25];
    const float* ch_b1  = (const float*)d_in[26];
    const float* ch_w2  = (const float*)d_in[27];
    const float* ch_b2  = (const float*)d_in[28];

    float* out_main = (float*)d_out;                     // [4,3,512,512]
    float* hid      = out_main + 4*3*512*512;            // [4,64,128,128]
    float* cell     = hid + 4*64*128*128;                // [4,64,128,128]

    void *pxc0, *pxc1, *poff, *pmask, *pxfin;
    cudaGetSymbolAddress(&pxc0, g_xcat0);
    cudaGetSymbolAddress(&pxc1, g_xcat1);
    cudaGetSymbolAddress(&poff,  g_off);
    cudaGetSymbolAddress(&pmask, g_mask);
    cudaGetSymbolAddress(&pxfin, g_xfin);
    float* xc0 = (float*)pxc0;
    float* xc1 = (float*)pxc1;
    float* off_p  = (float*)poff;
    float* mask_p = (float*)pmask;
    float* xfin_p = (float*)pxfin;

    cudaFuncSetAttribute(deform_kernel, cudaFuncAttributeMaxDynamicSharedMemorySize,
                         DF_SMEM_BYTES);

    dim3 rowGrid(128, B_);
    dim3 convGrid(4, 16, B_);

    copy_lr_kernel<<<(B_*3*HW/4 + 255)/256, 256>>>(X);          // launch 0

    lstm_kernel<<<rowGrid, 256>>>(X, lstm_w, lstm_b, hid, cell, xc0);   // 1

    conv_off_kernel<<<rowGrid, 256>>>(xc0, dw[0][0], dw[0][1],
                                      dw[0][2], dw[0][3], off_p, mask_p);  // 2
    deform_kernel<<<rowGrid, 256, DF_SMEM_BYTES>>>(xc0, dw[0][4], dw[0][5], xc1); // 3

    conv_off_kernel<<<rowGrid, 256>>>(xc1, dw[1][0], dw[1][1],
                                      dw[1][2], dw[1][3], off_p, mask_p);  // 4
    deform_kernel<<<rowGrid, 256, DF_SMEM_BYTES>>>(xc1, dw[1][4], dw[1][5], xc0); // 5 <- ncu

    conv_off_kernel<<<rowGrid, 256>>>(xc0, dw[2][0], dw[2][1],
                                      dw[2][2], dw[2][3], off_p, mask_p);
    deform_kernel<<<rowGrid, 256, DF_SMEM_BYTES>>>(xc0, dw[2][4], dw[2][5], xc1);

    conv_small_kernel<3><<<convGrid, 256>>>(xc1, conv_w, conv_b, xfin_p);

    pool_kernel<<<B_*3, 256>>>(xfin_p);
    ch_kernel<<<1, 64>>>(ch_w1, ch_b1, ch_w2, ch_b2);
    ddf_kernel<<<rowGrid, 256>>>(sp_w, sp_b, out_main);
}

// round 16
// speedup vs baseline: 1.0727x; 1.0727x over previous
#include <cuda_runtime.h>
#include <math.h>

#define HW   16384
#define B_   4
#define NCH  67

// ---------------- scratch ------------------------------------------------------
__device__ float g_xcat0[B_*NCH*HW];
__device__ float g_xcat1[B_*NCH*HW];
__device__ float g_off  [B_*18*HW];
__device__ float g_mask [B_*9*HW];
__device__ float g_xfin [B_*3*HW];
__device__ float g_ch   [B_*16*27];
__device__ float g_pool [B_*3];

__device__ __forceinline__ float sigm(float v){ return 1.f/(1.f+__expf(-v)); }

// ---- packed fp32x2 helpers ----------------------------------------------------
typedef unsigned long long ull;
__device__ __forceinline__ ull dup2(float v){
    ull r; asm("mov.b64 %0, {%1, %1};" : "=l"(r) : "f"(v)); return r;
}
__device__ __forceinline__ void ffma2(ull &d, ull a, ull b){
    asm("fma.rn.f32x2 %0, %1, %2, %0;" : "+l"(d) : "l"(a), "l"(b));
}
__device__ __forceinline__ ull add2(ull a, ull b){
    ull r; asm("add.rn.f32x2 %0, %1, %2;" : "=l"(r) : "l"(a), "l"(b)); return r;
}
__device__ __forceinline__ float2 unpk(ull v){
    float2 f; asm("mov.b64 {%0, %1}, %2;" : "=f"(f.x), "=f"(f.y) : "l"(v)); return f;
}

// ---------------- 0) copy LR into both xcat buffers (also shifts ncu index) ---
__global__ void copy_lr_kernel(const float* __restrict__ X)
{
    int i = blockIdx.x*256 + threadIdx.x;
    if (i >= B_*3*HW/4) return;
    int b = i / (3*HW/4), rem = i - b*(3*HW/4);
    float4 v = ((const float4*)X)[i];
    ((float4*)(g_xcat0 + (b*NCH + 64)*HW))[rem] = v;
    ((float4*)(g_xcat1 + (b*NCH + 64)*HW))[rem] = v;
}

// ---------------- 1) ConvLSTM: row-CTA, smem-staged, f32x2 k-pairs ------------
__global__ __launch_bounds__(256) void lstm_kernel(
    const float* __restrict__ X, const float* __restrict__ w,
    const float* __restrict__ bias,
    float* __restrict__ hid, float* __restrict__ cell, float* __restrict__ xcat)
{
    __shared__ float sX[9*132];
    __shared__ float2 sW2[32*3*28];
    __shared__ float2 sB2[32*3];

    int tid = threadIdx.x;
    int b = blockIdx.y, y = blockIdx.x;

    for (int i = tid; i < 2688; i += 256) {
        int kp = i / 84, rem = i - kp*84;
        int g = rem / 28, t = rem - g*28;
        int gbase = (g == 0) ? 0 : (g == 1) ? 128 : 192;
        float v0 = 0.f, v1 = 0.f;
        if (t < 27) {
            v0 = w[(gbase + 2*kp    )*603 + t];
            v1 = w[(gbase + 2*kp + 1)*603 + t];
        }
        sW2[i] = make_float2(v0, v1);
    }
    if (tid < 96) {
        int kp = tid / 3, g = tid - kp*3;
        int gbase = (g == 0) ? 0 : (g == 1) ? 128 : 192;
        sB2[tid] = make_float2(bias[gbase + 2*kp], bias[gbase + 2*kp + 1]);
    }
    if (tid < 9) {
        float* row = sX + tid*132;
        row[0] = 0.f; row[129] = 0.f; row[130] = 0.f; row[131] = 0.f;
    }
    for (int idx = tid; idx < 288; idx += 256) {
        int row9 = idx >> 5, q = idx & 31;
        int c = row9 / 3, r = row9 - c*3;
        int gy = y - 1 + r;
        float4 v = make_float4(0.f, 0.f, 0.f, 0.f);
        if (gy >= 0 && gy < 128)
            v = *(const float4*)(X + (b*3 + c)*HW + gy*128 + q*4);
        float* dst = sX + row9*132 + 1 + q*4;
        dst[0] = v.x; dst[1] = v.y; dst[2] = v.z; dst[3] = v.w;
    }
    __syncthreads();

    int px = tid & 127, kh = tid >> 7;

    ull win[28];
    #pragma unroll
    for (int c = 0; c < 3; c++)
        #pragma unroll
        for (int r = 0; r < 3; r++)
            #pragma unroll
            for (int q = 0; q < 3; q++)
                win[c*9 + r*3 + q] = dup2(sX[(c*3 + r)*132 + px + q]);
    win[27] = 0ull;

    int pix = y*128 + px;
    int kp0 = kh*16;
    #pragma unroll 1
    for (int kp = kp0; kp < kp0 + 16; kp++) {
        ull aI = *(const ull*)&sB2[kp*3 + 0];
        ull aO = *(const ull*)&sB2[kp*3 + 1];
        ull aG = *(const ull*)&sB2[kp*3 + 2];
        const ulonglong2* wI = (const ulonglong2*)(sW2 + (kp*3 + 0)*28);
        const ulonglong2* wO = (const ulonglong2*)(sW2 + (kp*3 + 1)*28);
        const ulonglong2* wG = (const ulonglong2*)(sW2 + (kp*3 + 2)*28);
        #pragma unroll
        for (int t2 = 0; t2 < 14; t2++) {
            ulonglong2 wi = wI[t2];
            ffma2(aI, wi.x, win[2*t2]); ffma2(aI, wi.y, win[2*t2 + 1]);
            ulonglong2 wo = wO[t2];
            ffma2(aO, wo.x, win[2*t2]); ffma2(aO, wo.y, win[2*t2 + 1]);
            ulonglong2 wg = wG[t2];
            ffma2(aG, wg.x, win[2*t2]); ffma2(aG, wg.y, win[2*t2 + 1]);
        }
        float2 ai = unpk(aI), ao = unpk(aO), ag = unpk(aG);
        float c0 = sigm(ai.x)*tanhf(ag.x);
        float c1 = sigm(ai.y)*tanhf(ag.y);
        float h0 = sigm(ao.x)*tanhf(c0);
        float h1 = sigm(ao.y)*tanhf(c1);
        int k0 = 2*kp;
        hid [(b*64 + k0    )*HW + pix] = h0;
        hid [(b*64 + k0 + 1)*HW + pix] = h1;
        cell[(b*64 + k0    )*HW + pix] = c0;
        cell[(b*64 + k0 + 1)*HW + pix] = c1;
        xcat[(b*NCH + k0    )*HW + pix] = h0;
        xcat[(b*NCH + k0 + 1)*HW + pix] = h1;
    }
}

// ---------------- 2) offset/mask conv, f32x2 packed GEMM (17-ch chunks) -------
__global__ __launch_bounds__(256) void conv_off_kernel(
    const float* __restrict__ xcat,
    const float* __restrict__ w0, const float* __restrict__ b0,
    const float* __restrict__ w1, const float* __restrict__ b1,
    float* __restrict__ out0, float* __restrict__ out1)
{
    __shared__ float sTile[17*3*132];
    __shared__ float sW[153*32];

    int tid = threadIdx.x;
    int pg = tid & 31;
    int og = tid >> 5;
    int b = blockIdx.y, y = blockIdx.x;
    int y0 = y - 1;

    ull acc[2][4];
    #pragma unroll
    for (int q = 0; q < 2; q++)
        #pragma unroll
        for (int p = 0; p < 4; p++) acc[q][p] = 0ull;

    for (int c0 = 0; c0 < 67; c0 += 17) {
        int cnt = (67 - c0) < 17 ? (67 - c0) : 17;
        for (int i = tid; i < cnt*3; i += 256) {
            int c = i / 3, r = i - c*3;
            float* row = sTile + c*396 + r*132;
            row[0] = 0.f; row[129] = 0.f; row[130] = 0.f; row[131] = 0.f;
        }
        for (int i = tid; i < cnt*96; i += 256) {
            int c = i / 96, rem = i - c*96;
            int r = rem >> 5, q = rem & 31;
            int gy = y0 + r;
            const float* src = xcat + (b*NCH + c0 + c)*HW;
            float4 v = make_float4(0.f, 0.f, 0.f, 0.f);
            if (gy >= 0 && gy < 128) v = *(const float4*)(src + gy*128 + q*4);
            float* dst = sTile + c*396 + r*132 + 1 + q*4;
            dst[0] = v.x; dst[1] = v.y; dst[2] = v.z; dst[3] = v.w;
        }
        int c09 = c0*9;
        for (int i = tid; i < cnt*288; i += 256) {
            int o = i & 31, tdx = i >> 5;
            float wv = 0.f;
            if (o < 18)      wv = w0[o*603 + c09 + tdx];
            else if (o < 27) wv = w1[(o-18)*603 + c09 + tdx];
            sW[tdx*32 + o] = wv;
        }
        __syncthreads();

        for (int c = 0; c < cnt; c++) {
            #pragma unroll
            for (int ky = 0; ky < 3; ky++) {
                const float* rb = sTile + c*396 + ky*132 + pg*4;
                float4 a4 = *(const float4*)rb;
                float2 a2 = *(const float2*)(rb + 4);
                ull vv[6];
                vv[0] = dup2(a4.x); vv[1] = dup2(a4.y); vv[2] = dup2(a4.z);
                vv[3] = dup2(a4.w); vv[4] = dup2(a2.x); vv[5] = dup2(a2.y);
                #pragma unroll
                for (int kx = 0; kx < 3; kx++) {
                    ulonglong2 w = *(const ulonglong2*)(sW + (c*9 + ky*3 + kx)*32 + og*4);
                    #pragma unroll
                    for (int p = 0; p < 4; p++) {
                        ffma2(acc[0][p], w.x, vv[kx + p]);
                        ffma2(acc[1][p], w.y, vv[kx + p]);
                    }
                }
            }
        }
        __syncthreads();
    }

    int pixb = y*128 + pg*4;
    #pragma unroll
    for (int wp = 0; wp < 2; wp++) {
        int o0 = og*4 + 2*wp;
        float2 a0 = unpk(acc[wp][0]), a1 = unpk(acc[wp][1]);
        float2 a2 = unpk(acc[wp][2]), a3 = unpk(acc[wp][3]);
        if (o0 < 18) {
            float bb = b0[o0];
            *(float4*)(out0 + (b*18 + o0)*HW + pixb) =
                make_float4(a0.x+bb, a1.x+bb, a2.x+bb, a3.x+bb);
        } else if (o0 < 27) {
            float bb = b1[o0-18];
            *(float4*)(out1 + (b*9 + (o0-18))*HW + pixb) =
                make_float4(2.f*sigm(a0.x+bb), 2.f*sigm(a1.x+bb),
                            2.f*sigm(a2.x+bb), 2.f*sigm(a3.x+bb));
        }
        int o1 = o0 + 1;
        if (o1 < 18) {
            float bb = b0[o1];
            *(float4*)(out0 + (b*18 + o1)*HW + pixb) =
                make_float4(a0.y+bb, a1.y+bb, a2.y+bb, a3.y+bb);
        } else if (o1 < 27) {
            float bb = b1[o1-18];
            *(float4*)(out1 + (b*9 + (o1-18))*HW + pixb) =
                make_float4(2.f*sigm(a0.y+bb), 2.f*sigm(a1.y+bb),
                            2.f*sigm(a2.y+bb), 2.f*sigm(a3.y+bb));
        }
    }
}

// ---------------- 2b) small direct conv (final 3-out fuse conv) ---------------
template<int COUT>
__global__ __launch_bounds__(256) void conv_small_kernel(
    const float* __restrict__ xcat,
    const float* __restrict__ w0, const float* __restrict__ b0,
    float* __restrict__ out0)
{
    __shared__ float sT[16*10*34];
    __shared__ float sW[COUT*16*9];
    int tid = threadIdx.x;
    int tx = tid & 31, ty = tid >> 5;
    int b = blockIdx.z;
    int x = blockIdx.x*32 + tx, y = blockIdx.y*8 + ty;
    int gx0 = blockIdx.x*32 - 1, gy0 = blockIdx.y*8 - 1;

    float acc[COUT];
    #pragma unroll
    for (int o = 0; o < COUT; o++) acc[o] = 0.f;

    for (int c0 = 0; c0 < 67; c0 += 16) {
        int cnt = (67 - c0) < 16 ? (67 - c0) : 16;
        for (int i = tid; i < cnt*340; i += 256) {
            int c = i / 340, rem = i - c*340;
            int r = rem / 34, col = rem - r*34;
            int gy = gy0 + r, gx = gx0 + col;
            const float* src = xcat + (b*NCH + c0 + c)*HW;
            sT[i] = (gy >= 0 && gy < 128 && gx >= 0 && gx < 128)
                  ? src[gy*128 + gx] : 0.f;
        }
        int wtot = COUT*cnt*9;
        for (int i = tid; i < wtot; i += 256) {
            int o = i / (cnt*9), rem = i - o*(cnt*9);
            sW[o*144 + rem] = w0[o*603 + c0*9 + rem];
        }
        __syncthreads();
        for (int c = 0; c < cnt; c++) {
            float win[9];
            #pragma unroll
            for (int r = 0; r < 3; r++)
                #pragma unroll
                for (int q = 0; q < 3; q++)
                    win[r*3+q] = sT[c*340 + (ty+r)*34 + (tx+q)];
            #pragma unroll
            for (int o = 0; o < COUT; o++) {
                #pragma unroll
                for (int t = 0; t < 9; t++)
                    acc[o] = fmaf(sW[o*144 + c*9 + t], win[t], acc[o]);
            }
        }
        __syncthreads();
    }
    int pix = y*128 + x;
    #pragma unroll
    for (int o = 0; o < COUT; o++)
        out0[(b*COUT + o)*HW + pix] = acc[o] + b0[o];
}

// ---------------- 3) deform: double-buffered chunk-18 pipeline, 4 CTA/SM ------
#define DF_SIDX   4608
#define DF_SV     (4608 + 1152)
#define SV_STRIDE (18*132)
#define DF_SWC    (DF_SV + 2*SV_STRIDE)
#define SWC_STRIDE (18*64)
#define DF_SMEM_BYTES ((DF_SWC + 2*SWC_STRIDE) * 4)
#define NCHUNK 34

__global__ __launch_bounds__(256, 4) void deform_kernel(
    const float* __restrict__ xcat,
    const float* __restrict__ wmain, const float* __restrict__ bias,
    float* __restrict__ out)
{
    extern __shared__ float smem[];
    float4* sWt = (float4*)smem;
    int*    sIdx= (int*)(smem + DF_SIDX);
    float*  sV  = smem + DF_SV;
    float*  sWc = smem + DF_SWC;

    int tid = threadIdx.x;
    int b = blockIdx.y, y = blockIdx.x;

    // ---- Phase A: bilinear meta (9 taps x 128 px) ----
    for (int e = tid; e < 1152; e += 256) {
        int p = e & 127, k = e >> 7;
        int pix = y*128 + p;
        float offy = g_off [(b*18 + 2*k    )*HW + pix];
        float offx = g_off [(b*18 + 2*k + 1)*HW + pix];
        float m    = g_mask[(b*9  + k      )*HW + pix];
        int ky = k / 3, kx = k - ky*3;
        float py = (float)(y + ky - 1) + offy;
        float px = (float)(p + kx - 1) + offx;
        float fy = floorf(py), fx = floorf(px);
        float wy = py - fy,    wx = px - fx;
        int iy = (int)fy, ix = (int)fx;
        bool vy0 = (iy   >= 0 && iy   <= 127);
        bool vy1 = (iy+1 >= 0 && iy+1 <= 127);
        bool vx0 = (ix   >= 0 && ix   <= 127);
        bool vx1 = (ix+1 >= 0 && ix+1 <= 127);
        float4 wv;
        wv.x = (1.f-wy)*(1.f-wx)*m * ((vy0 && vx0) ? 1.f : 0.f);
        wv.y = (1.f-wy)*wx      *m * ((vy0 && vx1) ? 1.f : 0.f);
        wv.z = wy*(1.f-wx)      *m * ((vy1 && vx0) ? 1.f : 0.f);
        wv.w = wy*wx            *m * ((vy1 && vx1) ? 1.f : 0.f);
        sWt[e] = wv;
        int iy0 = min(max(iy,   0), 127), iy1 = min(max(iy+1, 0), 127);
        int ix0 = min(max(ix,   0), 127), ix1 = min(max(ix+1, 0), 127);
        sIdx[e] = iy0 | (iy1 << 8) | (ix0 << 16) | (ix1 << 24);
    }

    const float* xb = xcat + b*NCH*HW;
    int pg = tid & 31, og = tid >> 5;

    ull acc[4][4];
    #pragma unroll
    for (int q = 0; q < 4; q++)
        #pragma unroll
        for (int p = 0; p < 4; p++) acc[q][p] = 0ull;

    auto stage = [&](int c, int buf) {
        int c0 = c*18;
        int cnt = (603 - c0) < 18 ? (603 - c0) : 18;
        int nch = cnt / 9;
        float* sVb = sV + buf*SV_STRIDE;
        float* sWb = sWc + buf*SWC_STRIDE;
        for (int i = tid; i < 18*64; i += 256) {
            int o = i & 63, j = i >> 6;
            sWb[j*64 + o] = (j < cnt) ? wmain[o*603 + c0 + j] : 0.f;
        }
        if (cnt < 18)
            for (int i = tid; i < (18 - cnt)*132; i += 256)
                sVb[cnt*132 + i] = 0.f;
        int cbase = (c0/9) * HW;
        for (int g = tid; g < 1152; g += 256) {
            int p = g & 127, k = g >> 7;
            float4 wt = sWt[g];
            int pk = sIdx[g];
            int iy0 =  pk        & 255, iy1 = (pk >> 8)  & 255;
            int ix0 = (pk >> 16) & 255, ix1 = (pk >> 24) & 255;
            int i0 = cbase + iy0*128 + ix0;
            int i1 = cbase + iy0*128 + ix1;
            int i2 = cbase + iy1*128 + ix0;
            int i3 = cbase + iy1*128 + ix1;
            float* sv = sVb + k*132 + p;
            if (nch == 2) {
                float a0 = __ldg(xb + i0),      a1 = __ldg(xb + i1);
                float a2 = __ldg(xb + i2),      a3 = __ldg(xb + i3);
                float b0 = __ldg(xb + i0 + HW), b1 = __ldg(xb + i1 + HW);
                float b2 = __ldg(xb + i2 + HW), b3 = __ldg(xb + i3 + HW);
                sv[0]     = wt.x*a0 + wt.y*a1 + wt.z*a2 + wt.w*a3;
                sv[9*132] = wt.x*b0 + wt.y*b1 + wt.z*b2 + wt.w*b3;
            } else {
                float a0 = __ldg(xb + i0), a1 = __ldg(xb + i1);
                float a2 = __ldg(xb + i2), a3 = __ldg(xb + i3);
                sv[0] = wt.x*a0 + wt.y*a1 + wt.z*a2 + wt.w*a3;
            }
        }
    };

    __syncthreads();
    stage(0, 0);
    __syncthreads();

    for (int c = 0; c < NCHUNK; c++) {
        int buf = c & 1;
        if (c + 1 < NCHUNK) stage(c + 1, buf ^ 1);

        const float* vp = sV + buf*SV_STRIDE + pg*4;
        const float* wp_ = sWc + buf*SWC_STRIDE + og*8;
        #pragma unroll 6
        for (int j = 0; j < 18; j++) {
            ulonglong2 wA = *(const ulonglong2*)(wp_ + j*64);
            ulonglong2 wB = *(const ulonglong2*)(wp_ + j*64 + 4);
            float4 v = *(const float4*)(vp + j*132);
            ull v0 = dup2(v.x), v1 = dup2(v.y), v2 = dup2(v.z), v3 = dup2(v.w);
            ffma2(acc[0][0], wA.x, v0); ffma2(acc[0][1], wA.x, v1);
            ffma2(acc[0][2], wA.x, v2); ffma2(acc[0][3], wA.x, v3);
            ffma2(acc[1][0], wA.y, v0); ffma2(acc[1][1], wA.y, v1);
            ffma2(acc[1][2], wA.y, v2); ffma2(acc[1][3], wA.y, v3);
            ffma2(acc[2][0], wB.x, v0); ffma2(acc[2][1], wB.x, v1);
            ffma2(acc[2][2], wB.x, v2); ffma2(acc[2][3], wB.x, v3);
            ffma2(acc[3][0], wB.y, v0); ffma2(acc[3][1], wB.y, v1);
            ffma2(acc[3][2], wB.y, v2); ffma2(acc[3][3], wB.y, v3);
        }
        __syncthreads();
    }

    int pixb = y*128 + pg*4;
    #pragma unroll
    for (int wp = 0; wp < 4; wp++) {
        int o0 = og*8 + 2*wp;
        float2 a0 = unpk(acc[wp][0]), a1 = unpk(acc[wp][1]);
        float2 a2 = unpk(acc[wp][2]), a3 = unpk(acc[wp][3]);
        float bb0 = bias[o0], bb1 = bias[o0+1];
        *(float4*)(out + (b*NCH + o0)*HW + pixb) =
            make_float4(a0.x+bb0, a1.x+bb0, a2.x+bb0, a3.x+bb0);
        *(float4*)(out + (b*NCH + o0+1)*HW + pixb) =
            make_float4(a0.y+bb1, a1.y+bb1, a2.y+bb1, a3.y+bb1);
    }
}

// ---------------- 4) global average pool --------------------------------------
__global__ void pool_kernel(const float* __restrict__ xf)
{
    __shared__ float red[256];
    int bc = blockIdx.x, tid = threadIdx.x;
    float s = 0.f;
    const float* p = xf + bc*HW;
    for (int i = tid; i < HW; i += 256) s += p[i];
    red[tid] = s; __syncthreads();
    for (int st = 128; st > 0; st >>= 1) {
        if (tid < st) red[tid] += red[tid + st];
        __syncthreads();
    }
    if (tid == 0) g_pool[bc] = red[0] * (1.f/HW);
}

// ---------------- 5) channel-filter MLP ---------------------------------------
__global__ void ch_kernel(const float* __restrict__ ch_w1, const float* __restrict__ ch_b1,
                          const float* __restrict__ ch_w2, const float* __restrict__ ch_b2)
{
    int t = threadIdx.x;
    if (t >= 64) return;
    int b = t >> 4, s = t & 15;
    float h1[4];
    #pragma unroll
    for (int m = 0; m < 4; m++) {
        float a = ch_b1[s*4 + m];
        #pragma unroll
        for (int c = 0; c < 3; c++) a = fmaf(g_pool[b*3 + c], ch_w1[(s*4 + m)*3 + c], a);
        h1[m] = fmaxf(a, 0.f);
    }
    for (int k = 0; k < 27; k++) {
        float a = ch_b2[s*27 + k];
        #pragma unroll
        for (int m = 0; m < 4; m++) a = fmaf(h1[m], ch_w2[(s*27 + k)*4 + m], a);
        g_ch[(b*16 + s)*27 + k] = a;
    }
}

// ---------------- 6) DDF up: f32x2 s-pair packed, 2 threads/px ----------------
__global__ __launch_bounds__(256) void ddf_kernel(
    const float* __restrict__ spw, const float* __restrict__ spb,
    float* __restrict__ out)
{
    __shared__ __align__(16) float2 sSpw2[8*9*28];
    __shared__ float2 sSpb2[72];
    __shared__ float2 sCh2[216];
    __shared__ float sX[3*3*132];

    int tid = threadIdx.x;
    int b = blockIdx.y, y = blockIdx.x;

    for (int idx = tid; idx < 2016; idx += 256) {
        int i = idx / 252, rem = idx - i*252;
        int k = rem / 28, j = rem - k*28;
        float v0 = 0.f, v1 = 0.f;
        if (j < 27) {
            v0 = spw[((2*i  )*9 + k)*27 + j];
            v1 = spw[((2*i+1)*9 + k)*27 + j];
        }
        sSpw2[idx] = make_float2(v0, v1);
    }
    if (tid < 72) {
        int i = tid / 9, k = tid - i*9;
        sSpb2[tid] = make_float2(spb[(2*i)*9 + k], spb[(2*i+1)*9 + k]);
    }
    if (tid < 216) {
        int i = tid / 27, j = tid - i*27;
        sCh2[tid] = make_float2(g_ch[b*432 + (2*i)*27 + j],
                                g_ch[b*432 + (2*i+1)*27 + j]);
    }
    if (tid < 9) {
        float* row = sX + tid*132;
        row[0] = 0.f; row[129] = 0.f; row[130] = 0.f; row[131] = 0.f;
    }
    for (int idx = tid; idx < 288; idx += 256) {
        int row9 = idx >> 5, q = idx & 31;
        int c = row9 / 3, r = row9 - c*3;
        int gy = y - 1 + r;
        float4 v = make_float4(0.f, 0.f, 0.f, 0.f);
        if (gy >= 0 && gy < 128)
            v = *(const float4*)(g_xfin + (b*3 + c)*HW + gy*128 + q*4);
        float* dst = sX + row9*132 + 1 + q*4;
        dst[0] = v.x; dst[1] = v.y; dst[2] = v.z; dst[3] = v.w;
    }
    __syncthreads();

    int px = tid & 127, half = tid >> 7;

    ull winD[28];
    #pragma unroll
    for (int c = 0; c < 3; c++)
        #pragma unroll
        for (int r = 0; r < 3; r++)
            #pragma unroll
            for (int q = 0; q < 3; q++)
                winD[c*9 + r*3 + q] = dup2(sX[(c*3 + r)*132 + px + q]);
    winD[27] = 0ull;

    float* ob = out + b*3*(512*512);
    int i0 = half*4;
    #pragma unroll 1
    for (int i = i0; i < i0 + 4; i++) {
        ull a0 = 0ull, a1 = 0ull, a2 = 0ull;
        #pragma unroll
        for (int k = 0; k < 9; k++) {
            ull spv = *(const ull*)&sSpb2[i*9 + k];
            const ulonglong2* w2 = (const ulonglong2*)(sSpw2 + (i*9 + k)*28);
            #pragma unroll
            for (int j2 = 0; j2 < 14; j2++) {
                ulonglong2 w = w2[j2];
                ffma2(spv, w.x, winD[j2*2]);
                ffma2(spv, w.y, winD[j2*2 + 1]);
            }
            ull t0 = add2(*(const ull*)&sCh2[i*27 + k],      spv);
            ull t1 = add2(*(const ull*)&sCh2[i*27 + 9 + k],  spv);
            ull t2 = add2(*(const ull*)&sCh2[i*27 + 18 + k], spv);
            ffma2(a0, winD[k],      t0);
            ffma2(a1, winD[9 + k],  t1);
            ffma2(a2, winD[18 + k], t2);
        }
        float2 r0 = unpk(a0), r1 = unpk(a1), r2 = unpk(a2);
        int s0 = 2*i, s1 = 2*i + 1;
        int oy0 = (y << 2) + (s0 >> 2), ox0 = (px << 2) + (s0 & 3);
        int oy1 = (y << 2) + (s1 >> 2), ox1 = (px << 2) + (s1 & 3);
        ob[0*262144 + oy0*512 + ox0] = fminf(fmaxf(r0.x, 0.f), 255.f);
        ob[1*262144 + oy0*512 + ox0] = fminf(fmaxf(r1.x, 0.f), 255.f);
        ob[2*262144 + oy0*512 + ox0] = fminf(fmaxf(r2.x, 0.f), 255.f);
        ob[0*262144 + oy1*512 + ox1] = fminf(fmaxf(r0.y, 0.f), 255.f);
        ob[1*262144 + oy1*512 + ox1] = fminf(fmaxf(r1.y, 0.f), 255.f);
        ob[2*262144 + oy1*512 + ox1] = fminf(fmaxf(r2.y, 0.f), 255.f);
    }
}

// ---------------- host orchestration ------------------------------------------
extern "C" void kernel_launch(void* const* d_in, const int* in_sizes, int n_in,
                              void* d_out, int out_size)
{
    const float* X      = (const float*)d_in[0];
    const float* lstm_w = (const float*)d_in[1];
    const float* lstm_b = (const float*)d_in[2];
    const float* dw[3][6];
    for (int i = 0; i < 3; i++)
        for (int j = 0; j < 6; j++)
            dw[i][j] = (const float*)d_in[3 + i*6 + j];   // ow, ob, mw, mb, w, b
    const float* conv_w = (const float*)d_in[21];
    const float* conv_b = (const float*)d_in[22];
    const float* sp_w   = (const float*)d_in[23];
    const float* sp_b   = (const float*)d_in[24];
    const float* ch_w1  = (const float*)d_in[25];
    const float* ch_b1  = (const float*)d_in[26];
    const float* ch_w2  = (const float*)d_in[27];
    const float* ch_b2  = (const float*)d_in[28];

    float* out_main = (float*)d_out;                     // [4,3,512,512]
    float* hid      = out_main + 4*3*512*512;            // [4,64,128,128]
    float* cell     = hid + 4*64*128*128;                // [4,64,128,128]

    void *pxc0, *pxc1, *poff, *pmask, *pxfin;
    cudaGetSymbolAddress(&pxc0, g_xcat0);
    cudaGetSymbolAddress(&pxc1, g_xcat1);
    cudaGetSymbolAddress(&poff,  g_off);
    cudaGetSymbolAddress(&pmask, g_mask);
    cudaGetSymbolAddress(&pxfin, g_xfin);
    float* xc0 = (float*)pxc0;
    float* xc1 = (float*)pxc1;
    float* off_p  = (float*)poff;
    float* mask_p = (float*)pmask;
    float* xfin_p = (float*)pxfin;

    cudaFuncSetAttribute(deform_kernel, cudaFuncAttributeMaxDynamicSharedMemorySize,
                         DF_SMEM_BYTES);

    dim3 rowGrid(128, B_);
    dim3 convGrid(4, 16, B_);

    copy_lr_kernel<<<(B_*3*HW/4 + 255)/256, 256>>>(X);          // launch 0

    lstm_kernel<<<rowGrid, 256>>>(X, lstm_w, lstm_b, hid, cell, xc0);   // 1

    conv_off_kernel<<<rowGrid, 256>>>(xc0, dw[0][0], dw[0][1],
                                      dw[0][2], dw[0][3], off_p, mask_p);  // 2
    deform_kernel<<<rowGrid, 256, DF_SMEM_BYTES>>>(xc0, dw[0][4], dw[0][5], xc1); // 3

    conv_off_kernel<<<rowGrid, 256>>>(xc1, dw[1][0], dw[1][1],
                                      dw[1][2], dw[1][3], off_p, mask_p);  // 4
    deform_kernel<<<rowGrid, 256, DF_SMEM_BYTES>>>(xc1, dw[1][4], dw[1][5], xc0); // 5 <- ncu

    conv_off_kernel<<<rowGrid, 256>>>(xc0, dw[2][0], dw[2][1],
                                      dw[2][2], dw[2][3], off_p, mask_p);
    deform_kernel<<<rowGrid, 256, DF_SMEM_BYTES>>>(xc0, dw[2][4], dw[2][5], xc1);

    conv_small_kernel<3><<<convGrid, 256>>>(xc1, conv_w, conv_b, xfin_p);

    pool_kernel<<<B_*3, 256>>>(xfin_p);
    ch_kernel<<<1, 64>>>(ch_w1, ch_b1, ch_w2, ch_b2);
    ddf_kernel<<<rowGrid, 256>>>(sp_w, sp_b, out_main);
}